// round 5
// baseline (speedup 1.0000x reference)
#include <cuda_runtime.h>
#include <cstdint>

// ---------------- problem constants ----------------
#define B      128
#define D      768
#define POOL   100
#define LG     6
#define LE     6
#define GLEN   5
#define ELEN   20
#define H      12
#define HD     64
#define TOPK   5

// Output rows: one row = HD floats = 16 float4 = 256 bytes.
#define G_ROWS     (LG*2*B*H*GLEN)              // 92,160
#define E_ROWS     (LE*2*B*H*(TOPK*ELEN))       // 1,843,200
#define E_HALF     (E_ROWS/2)                   // 921,600 (= ld offset of 6)
#define G_PAIRS    (G_ROWS*8)                   // 737,280
#define E_HALF_PAIRS (E_HALF*8)                 // 7,372,800

#define SEL_BLOCKS 128
#define G_BLOCKS   (G_PAIRS/512)                // 1,440 (exact)

// scratch for selected indices (no cudaMalloc allowed)
__device__ int d_idx[B * TOPK];

// ---------------------------------------------------------------------------
// Kernel 1 (fused): blocks 0..127 do top-5 selection (one query row each);
// blocks 128.. write the g region. The two run concurrently — selection
// latency is hidden under the g-region memory traffic.
// ---------------------------------------------------------------------------
__global__ __launch_bounds__(512) void select_and_g_kernel(
        const float4* __restrict__ query4,
        const float4* __restrict__ keys4,
        const float4* __restrict__ g4,
        float4* __restrict__ out4) {
    if (blockIdx.x < SEL_BLOCKS) {
        // ---- selection: warp-per-dot-product, qn dropped (ranking-invariant)
        const int b    = blockIdx.x;
        const int t    = threadIdx.x;
        const int warp = t >> 5;
        const int lane = t & 31;

        __shared__ float sims[POOL];

        const float4* qr = query4 + (size_t)b * (D / 4);
        float4 fq[6];
        #pragma unroll
        for (int j = 0; j < 6; j++) fq[j] = __ldg(&qr[lane + 32 * j]);

        for (int p = warp; p < POOL; p += 16) {
            const float4* kr = keys4 + (size_t)p * (D / 4);
            float dot = 0.f, kk = 0.f;
            #pragma unroll
            for (int j = 0; j < 6; j++) {
                float4 kv = __ldg(&kr[lane + 32 * j]);
                dot = fmaf(fq[j].x, kv.x, dot);
                dot = fmaf(fq[j].y, kv.y, dot);
                dot = fmaf(fq[j].z, kv.z, dot);
                dot = fmaf(fq[j].w, kv.w, dot);
                kk  = fmaf(kv.x, kv.x, kk);
                kk  = fmaf(kv.y, kv.y, kk);
                kk  = fmaf(kv.z, kv.z, kk);
                kk  = fmaf(kv.w, kv.w, kk);
            }
            #pragma unroll
            for (int o = 16; o > 0; o >>= 1) {
                dot += __shfl_xor_sync(0xFFFFFFFFu, dot, o);
                kk  += __shfl_xor_sync(0xFFFFFFFFu, kk,  o);
            }
            if (lane == 0) {
                float kn = fmaxf(sqrtf(kk), 1e-12f);
                sims[p] = dot / kn;
            }
        }
        __syncthreads();

        // warp 0: parallel top-5 argmax, tie-break = lowest index
        if (warp == 0) {
            #pragma unroll
            for (int k = 0; k < TOPK; k++) {
                float best = -3.0e38f;
                int   bi   = POOL;
                #pragma unroll
                for (int j = 0; j < 4; j++) {
                    int p = lane + 32 * j;
                    if (p < POOL) {
                        float v = sims[p];
                        if (v > best) { best = v; bi = p; }
                    }
                }
                #pragma unroll
                for (int o = 16; o > 0; o >>= 1) {
                    float ov = __shfl_xor_sync(0xFFFFFFFFu, best, o);
                    int   oi = __shfl_xor_sync(0xFFFFFFFFu, bi,   o);
                    if (ov > best || (ov == best && oi < bi)) { best = ov; bi = oi; }
                }
                if (lane == 0) {
                    d_idx[b * TOPK + k] = bi;
                    sims[bi] = -3.0e38f;
                }
                __syncwarp();
            }
        }
    } else {
        // ---- g region: out[ld,b,h,gl,:] = g_prompt[ld,gl,h,:]
        int gid = (blockIdx.x - SEL_BLOCKS) * 512 + threadIdx.x;  // < G_PAIRS (exact)
        const int c4h = gid & 7;
        const int row = gid >> 3;
        // row = ((ld*B + b)*H + h)*GLEN + gl
        int v  = row;
        int gl = v % GLEN; v /= GLEN;
        int h  = v % H;    v /= H;
        v >>= 7;                               // drop b
        int ld = v;                            // 0..11
        const float4* src = &g4[(((ld * GLEN + gl) * H + h) << 4) + c4h];
        float4 v0 = __ldg(src);
        float4 v1 = __ldg(src + 8);
        float4* dst = out4 + ((long long)row << 4) + c4h;
        __stcs(dst,     v0);
        __stcs(dst + 8, v1);
    }
}

// ---------------------------------------------------------------------------
// Kernel 2: e-region writer. One thread = one (row, half-slot) in the first
// half PLUS the twin row at +E_HALF (which is exactly ld -> ld+6: same b,h,m,
// same prompt index). One index decomposition serves 4 loads + 4 stores;
// every access covers 4 full 128B lines (perfect coalescing), MLP=4.
//   out[ld,b,h,m,:] = pool[idx[b][m/ELEN], ld, m%ELEN, h, :]
// ---------------------------------------------------------------------------
#define POOL_LD_STRIDE4  (ELEN * H * 16)          // float4 stride for ld+1 in pool
#define OUT_HALF_STRIDE4 ((long long)E_HALF * 16) // float4 stride for row+E_HALF

__global__ __launch_bounds__(256) void e_write_kernel(
        const float4* __restrict__ pool4,
        float4* __restrict__ out4) {
    int gid = blockIdx.x * blockDim.x + threadIdx.x;
    if (gid >= E_HALF_PAIRS) return;

    const int c4h = gid & 7;
    const int row = gid >> 3;              // 0..E_HALF-1  (ld in 0..5)

    // row = ((ld*B + b)*H + h)*100 + m
    int v  = row;
    int m  = v % (TOPK * ELEN); v /= (TOPK * ELEN);
    int h  = v % H;             v /= H;
    int b  = v & 127;           v >>= 7;
    int ld = v;                            // 0..5
    int k  = m / ELEN;
    int e  = m - k * ELEN;
    int p  = __ldg(&d_idx[b * TOPK + k]);

    const float4* src0 = &pool4[((((p * 12 + ld) * ELEN + e) * H + h) << 4) + c4h];
    const float4* src1 = src0 + 6 * POOL_LD_STRIDE4;   // ld+6

    float4 a0 = __ldg(src0);
    float4 a1 = __ldg(src0 + 8);
    float4 b0 = __ldg(src1);
    float4 b1 = __ldg(src1 + 8);

    float4* dst0 = out4 + (((long long)G_ROWS + row) << 4) + c4h;
    float4* dst1 = dst0 + OUT_HALF_STRIDE4;

    __stcs(dst0,     a0);
    __stcs(dst0 + 8, a1);
    __stcs(dst1,     b0);
    __stcs(dst1 + 8, b1);
}

// ---------------------------------------------------------------------------
extern "C" void kernel_launch(void* const* d_in, const int* in_sizes, int n_in,
                              void* d_out, int out_size) {
    const float* query = (const float*)d_in[0];
    const float* gprm  = (const float*)d_in[1];
    const float* pool  = (const float*)d_in[2];
    const float* keys  = (const float*)d_in[3];
    float* out = (float*)d_out;

    // 1. fused: selection (128 blocks) + g-region writes (1440 blocks)
    select_and_g_kernel<<<SEL_BLOCKS + G_BLOCKS, 512>>>(
        (const float4*)query, (const float4*)keys,
        (const float4*)gprm, (float4*)out);

    // 2. e-region writer (depends on d_idx; same stream => ordered)
    {
        const int threads = 256;
        int blocks = (E_HALF_PAIRS + threads - 1) / threads;   // 28,800
        e_write_kernel<<<blocks, threads>>>((const float4*)pool, (float4*)out);
    }
}